// round 6
// baseline (speedup 1.0000x reference)
#include <cuda_runtime.h>
#include <math.h>

// CTC loss forward, fp32 log2-domain lse3, asynchronous warp wavefront.
// One CTA per batch element. Alpha register-resident (1 state/thread),
// neighbor values via shfl, warp-boundary value via smem ring + acq/rel flags.
// x (T,N,C) f32 log-softmax, y (N,S) i32, ilen (N) i32, tlen (N) i32.

#define T_DIM 2048
#define N_DIM 64
#define C_DIM 256
#define S_DIM 256
#define NC    (N_DIM * C_DIM)

#define NSTATE 544            // E_max = 513 -> 17 warps
#define NWARP  17
#define D_RING 32             // ring depth (power of 2)
#define NEGF   (-1.0e30f)
#define LOG2E_F 1.4426950408889634f

__device__ float g_losses[N_DIM];

__device__ __forceinline__ float ex2(float v) {
    float r; asm("ex2.approx.ftz.f32 %0, %1;" : "=f"(r) : "f"(v)); return r;
}
__device__ __forceinline__ float lg2(float v) {
    float r; asm("lg2.approx.f32 %0, %1;" : "=f"(r) : "f"(v)); return r;
}
__device__ __forceinline__ int ld_acq(const int* p) {
    int v; unsigned a = (unsigned)__cvta_generic_to_shared(p);
    asm volatile("ld.acquire.cta.shared.b32 %0, [%1];" : "=r"(v) : "r"(a) : "memory");
    return v;
}
__device__ __forceinline__ void st_rel(int* p, int v) {
    unsigned a = (unsigned)__cvta_generic_to_shared(p);
    asm volatile("st.release.cta.shared.b32 [%0], %1;" :: "r"(a), "r"(v) : "memory");
}

__global__ __launch_bounds__(NSTATE, 1)
void ctc_fwd_kernel(const float* __restrict__ x,
                    const int*   __restrict__ y,
                    const int*   __restrict__ ilen,
                    const int*   __restrict__ tlen)
{
    __shared__ float ring[NWARP][D_RING];   // boundary value (state 32w+31) per time
    __shared__ int   prod_flag[NWARP];      // last time published by warp w
    __shared__ int   cons_flag[NWARP];      // last time consumed by warp w (from w-1)
    __shared__ float Afin[NSTATE];

    const int n    = blockIdx.x;
    const int tid  = threadIdx.x;
    const int w    = tid >> 5;
    const int lane = tid & 31;
    const int s    = tid;

    const int Ti     = ilen[n];
    const int L      = tlen[n];
    const int Tend   = Ti - 1;
    const int E_used = 2 * L + 1;

    // per-state constants
    int  lbl  = 0;
    bool skip = false;
    if (s & 1) {
        const int k = (s - 1) >> 1;
        if (k < S_DIM) {
            lbl = y[n * S_DIM + k];
            skip = (k > 0) && (lbl != 0) && (lbl != y[n * S_DIM + k - 1]);
        }
    }
    const bool active      = (s < E_used);
    const bool warp_active = ((w << 5) < E_used);
    const float* gaddr = x + (size_t)n * C_DIM + lbl;   // + t*NC per step

    // flags init (inactive warps park at MAX so nobody ever waits on them)
    if (lane == 0) {
        prod_flag[w] = warp_active ? 0 : 0x7fffffff;
        cons_flag[w] = warp_active ? 0 : 0x7fffffff;
    }

    // alpha_0
    float a = (active && s < 2) ? LOG2E_F * __ldg(gaddr) : NEGF;
    if (lane == 31 && w < NWARP - 1) ring[w][0] = a;    // time-0 boundary
    __syncthreads();                                    // publishes init state

    if (warp_active) {
        // lp prefetch pipeline (4 deep)
        float v0 = 0.f, v1 = 0.f, v2 = 0.f, v3 = 0.f;
        if (1 <= Tend) v0 = __ldg(gaddr + (size_t)1 * NC);
        if (2 <= Tend) v1 = __ldg(gaddr + (size_t)2 * NC);
        if (3 <= Tend) v2 = __ldg(gaddr + (size_t)3 * NC);
        if (4 <= Tend) v3 = __ldg(gaddr + (size_t)4 * NC);

        int prod_seen = 0;   // lower bound of prod_flag[w-1]
        int cons_seen = 0;   // lower bound of cons_flag[w+1]

        #define STEP(V, TT)                                                   \
        {                                                                     \
            const int t_ = (TT);                                              \
            float rp = NEGF;                                                  \
            if (w > 0) {                                                      \
                if (prod_seen < t_ - 1) {                                     \
                    int f;                                                    \
                    do { f = ld_acq(&prod_flag[w - 1]); } while (f < t_ - 1); \
                    prod_seen = f;                                            \
                }                                                             \
                if (lane == 0) {                                              \
                    rp = ring[w - 1][(t_ - 1) & (D_RING - 1)];                \
                    st_rel(&cons_flag[w], t_ - 1);                            \
                }                                                             \
                rp = __shfl_sync(0xffffffffu, rp, 0);                         \
            }                                                                 \
            float a2 = __shfl_up_sync(0xffffffffu, a, 1);                     \
            float a3 = __shfl_up_sync(0xffffffffu, a, 2);                     \
            if (lane == 0) a2 = rp;                                           \
            if (lane == 1) a3 = rp;                                           \
            a3 = skip ? a3 : NEGF;                                            \
            const float g_ = fmaxf(a, a2);                                    \
            const float s_ = fminf(a, a2);                                    \
            const float m_ = fmaxf(g_, a3);                                   \
            const float l_ = fminf(g_, a3);                                   \
            const float e_ = 1.0f + ex2(s_ - m_) + ex2(l_ - m_);              \
            const float nv = fmaf(LOG2E_F, (V), m_ + lg2(e_));                \
            a = active ? nv : NEGF;                                           \
            if (w < NWARP - 1) {                                              \
                if (cons_seen < t_ - D_RING) {                                \
                    int f;                                                    \
                    do { f = ld_acq(&cons_flag[w + 1]); } while (f < t_ - D_RING); \
                    cons_seen = f;                                            \
                }                                                             \
                if (lane == 31) {                                             \
                    ring[w][t_ & (D_RING - 1)] = a;                           \
                    st_rel(&prod_flag[w], t_);                                \
                }                                                             \
            }                                                                 \
        }

        for (int t = 1; t <= Tend; t += 4) {
            STEP(v0, t);
            if (t + 4 <= Tend) v0 = __ldg(gaddr + (size_t)(t + 4) * NC);
            if (t + 1 <= Tend) {
                STEP(v1, t + 1);
                if (t + 5 <= Tend) v1 = __ldg(gaddr + (size_t)(t + 5) * NC);
            }
            if (t + 2 <= Tend) {
                STEP(v2, t + 2);
                if (t + 6 <= Tend) v2 = __ldg(gaddr + (size_t)(t + 6) * NC);
            }
            if (t + 3 <= Tend) {
                STEP(v3, t + 3);
                if (t + 7 <= Tend) v3 = __ldg(gaddr + (size_t)(t + 7) * NC);
            }
        }
        #undef STEP
    }

    __syncthreads();
    if (active) Afin[s] = a;
    __syncthreads();

    if (tid == 0) {
        const float u1 = Afin[2 * L - 1];
        const float u2 = Afin[2 * L];
        const float m  = fmaxf(u1, u2);
        const float mn = fminf(u1, u2);
        const float ll2 = m + lg2(1.0f + ex2(mn - m));   // log2-likelihood
        const double LN2 = 0.69314718055994530942;
        const int Ld = (L > 0) ? L : 1;
        g_losses[n] = (float)(-((double)ll2 * LN2) / (double)Ld);
    }
}

__global__ void ctc_reduce_kernel(float* __restrict__ out)
{
    if (blockIdx.x == 0 && threadIdx.x == 0) {
        double acc = 0.0;
        #pragma unroll
        for (int i = 0; i < N_DIM; ++i) acc += (double)g_losses[i];  // fixed order
        out[0] = (float)(acc / (double)N_DIM);
    }
}

extern "C" void kernel_launch(void* const* d_in, const int* in_sizes, int n_in,
                              void* d_out, int out_size)
{
    const float* x  = (const float*)d_in[0];
    const int*   y  = (const int*)  d_in[1];
    const int*   il = (const int*)  d_in[2];
    const int*   tl = (const int*)  d_in[3];
    float* out = (float*)d_out;

    ctc_fwd_kernel<<<N_DIM, NSTATE>>>(x, y, il, tl);
    ctc_reduce_kernel<<<1, 32>>>(out);
}

// round 7
// speedup vs baseline: 1.1485x; 1.1485x over previous
#include <cuda_runtime.h>
#include <math.h>

// CTC loss forward, fp32 log2-domain, pair-per-thread with redundant-halo
// chunking: 8 barrier-free steps per __syncthreads pair.
// Warp layout: lane l holds label-pair p = 24*w + l - 8.
//   lanes 0..7  = halo pairs (redundant copy of left warp's top 8 pairs)
//   lanes 8..31 = main pairs
// Halo validity shrinks 1 lane/step -> exactly 8 steps per chunk.
// x (T,N,C) f32 log-softmax, y (N,S) i32, ilen (N) i32, tlen (N) i32.

#define N_DIM 64
#define C_DIM 256
#define S_DIM 256
#define NC    (N_DIM * C_DIM)

#define NWARP   11
#define MAINP   24
#define HALO    8
#define THREADS (NWARP * 32)
#define NEGF    (-1.0e30f)
#define L2E     1.4426950408889634f

__device__ float g_losses[N_DIM];

__device__ __forceinline__ float ex2(float v) {
    float r; asm("ex2.approx.ftz.f32 %0, %1;" : "=f"(r) : "f"(v)); return r;
}
__device__ __forceinline__ float lg2(float v) {
    float r; asm("lg2.approx.f32 %0, %1;" : "=f"(r) : "f"(v)); return r;
}

__global__ __launch_bounds__(THREADS, 1)
void ctc_fwd_kernel(const float* __restrict__ x,
                    const int*   __restrict__ y,
                    const int*   __restrict__ ilen,
                    const int*   __restrict__ tlen)
{
    __shared__ float exch[NWARP][HALO][2];   // boundary pair values per chunk
    __shared__ float Afin[2 * S_DIM + 2];    // final alpha (514 states)

    const int n    = blockIdx.x;
    const int tid  = threadIdx.x;
    const int w    = tid >> 5;
    const int l    = tid & 31;

    const int Ti     = ilen[n];
    const int L      = tlen[n];
    const int Tend   = Ti - 1;
    const int E_used = 2 * L + 1;

    const int p = MAINP * w + l - HALO;      // label-pair index (may be <0 / >256)
    const bool act_e = (p >= 0) && (2 * p     < E_used);
    const bool act_o = (p >= 0) && (2 * p + 1 < E_used);

    int  lbl  = 0;
    bool skip = false;
    if (p >= 0 && p < S_DIM) {
        lbl  = y[n * S_DIM + p];
        skip = (p > 0) && (lbl != y[n * S_DIM + p - 1]);
    }
    const float* gb = x + (size_t)n * C_DIM;     // blank column (+ t*NC)
    const float* gl = gb + lbl;                  // label column (+ t*NC)

    // ---- alpha_0 ----
    float ae = NEGF, ao = NEGF;
    if (p == 0) {                                // states 0 and 1
        ae = L2E * __ldg(gb);
        ao = L2E * __ldg(gl);
    }

    // ---- prefetch rings (depth 4), rows 1..4 ----
    float vl0 = 0.f, vl1 = 0.f, vl2 = 0.f, vl3 = 0.f;
    float vb0 = 0.f, vb1 = 0.f, vb2 = 0.f, vb3 = 0.f;
    if (1 <= Tend) { vl0 = __ldg(gl + (size_t)1 * NC); vb0 = __ldg(gb + (size_t)1 * NC); }
    if (2 <= Tend) { vl1 = __ldg(gl + (size_t)2 * NC); vb1 = __ldg(gb + (size_t)2 * NC); }
    if (3 <= Tend) { vl2 = __ldg(gl + (size_t)3 * NC); vb2 = __ldg(gb + (size_t)3 * NC); }
    if (4 <= Tend) { vl3 = __ldg(gl + (size_t)4 * NC); vb3 = __ldg(gb + (size_t)4 * NC); }

    #define SUB(J, VL, VB)                                                    \
    if (t0 + (J) <= Tend) {                                                   \
        float aop = __shfl_up_sync(0xffffffffu, ao, 1);                       \
        if (l == 0) aop = NEGF;                                               \
        /* even state 2p: lse2(ae, a[2p-1]) + lp_blank */                     \
        const float me = fmaxf(ae, aop);                                      \
        const float ne = fminf(ae, aop);                                      \
        float re = me + lg2(1.0f + ex2(ne - me));                             \
        re = fmaf(L2E, (VB), re);                                             \
        /* odd state 2p+1: lse3(ao, ae, skip? a[2p-1]) + lp_lbl */            \
        const float a3 = skip ? aop : NEGF;                                   \
        const float g_ = fmaxf(ao, ae);                                       \
        const float s_ = fminf(ao, ae);                                       \
        const float m_ = fmaxf(g_, a3);                                       \
        const float q_ = fminf(g_, a3);                                       \
        float ro = m_ + lg2(1.0f + ex2(s_ - m_) + ex2(q_ - m_));              \
        ro = fmaf(L2E, (VL), ro);                                             \
        ae = act_e ? re : NEGF;                                               \
        ao = act_o ? ro : NEGF;                                               \
        const int tn = t0 + (J) + 4;                                          \
        if (tn <= Tend) {                                                     \
            VL = __ldg(gl + (size_t)tn * NC);                                 \
            VB = __ldg(gb + (size_t)tn * NC);                                 \
        }                                                                     \
    }

    // ---- chunked main loop ----
    for (int t0 = 1; t0 <= Tend; t0 += HALO) {
        SUB(0, vl0, vb0)
        SUB(1, vl1, vb1)
        SUB(2, vl2, vb2)
        SUB(3, vl3, vb3)
        SUB(4, vl0, vb0)
        SUB(5, vl1, vb1)
        SUB(6, vl2, vb2)
        SUB(7, vl3, vb3)

        // halo refill: lanes 24..31 publish pairs 24w+16..24w+23
        // (= warp (w+1)'s halo pairs 24(w+1)-8 .. 24(w+1)-1)
        if (l >= 32 - HALO) { exch[w][l - (32 - HALO)][0] = ae;
                              exch[w][l - (32 - HALO)][1] = ao; }
        __syncthreads();
        if (l < HALO) {
            if (w > 0) { ae = exch[w - 1][l][0]; ao = exch[w - 1][l][1]; }
            else       { ae = NEGF;              ao = NEGF; }
        }
        __syncthreads();   // protect exch against next chunk's overwrite
    }
    #undef SUB

    // ---- epilogue ----
    if (l >= HALO) {
        if (act_e) Afin[2 * p]     = ae;
        if (act_o) Afin[2 * p + 1] = ao;
    }
    __syncthreads();

    if (tid == 0) {
        const float u1 = Afin[2 * L - 1];
        const float u2 = Afin[2 * L];
        const float m  = fmaxf(u1, u2);
        const float mn = fminf(u1, u2);
        const float ll2 = m + lg2(1.0f + ex2(mn - m));   // log2-likelihood
        const double LN2 = 0.69314718055994530942;
        const int Ld = (L > 0) ? L : 1;
        g_losses[n] = (float)(-((double)ll2 * LN2) / (double)Ld);
    }
}

__global__ void ctc_reduce_kernel(float* __restrict__ out)
{
    if (blockIdx.x == 0 && threadIdx.x == 0) {
        double acc = 0.0;
        #pragma unroll
        for (int i = 0; i < N_DIM; ++i) acc += (double)g_losses[i];  // fixed order
        out[0] = (float)(acc / (double)N_DIM);
    }
}

extern "C" void kernel_launch(void* const* d_in, const int* in_sizes, int n_in,
                              void* d_out, int out_size)
{
    const float* x  = (const float*)d_in[0];
    const int*   y  = (const int*)  d_in[1];
    const int*   il = (const int*)  d_in[2];
    const int*   tl = (const int*)  d_in[3];
    float* out = (float*)d_out;

    ctc_fwd_kernel<<<N_DIM, THREADS>>>(x, y, il, tl);
    ctc_reduce_kernel<<<1, 32>>>(out);
}

// round 8
// speedup vs baseline: 1.4136x; 1.2308x over previous
#include <cuda_runtime.h>
#include <math.h>

// CTC loss forward, fp32 log2-domain, PAIR-per-thread smem/barrier design.
// Thread p owns states (2p, 2p+1); only odd states shared via smem.
// x (T,N,C) f32 log-softmax, y (N,S) i32, ilen (N) i32, tlen (N) i32.

#define N_DIM 64
#define C_DIM 256
#define S_DIM 256
#define NC    (N_DIM * C_DIM)

#define NPAIR    257          // pairs 0..256 (state 512 = even of pair 256)
#define NTHREADS 288          // 9 warps
#define NEGF     (-1.0e30f)
#define L2E      1.4426950408889634f

__device__ float g_losses[N_DIM];

__device__ __forceinline__ float ex2(float v) {
    float r; asm("ex2.approx.ftz.f32 %0, %1;" : "=f"(r) : "f"(v)); return r;
}
__device__ __forceinline__ float lg2(float v) {
    float r; asm("lg2.approx.f32 %0, %1;" : "=f"(r) : "f"(v)); return r;
}

__global__ __launch_bounds__(NTHREADS, 1)
void ctc_fwd_kernel(const float* __restrict__ x,
                    const int*   __restrict__ y,
                    const int*   __restrict__ ilen,
                    const int*   __restrict__ tlen)
{
    __shared__ float Aod[2][NTHREADS + 2];   // odd-state vals; slot 0 = NEG pad
    __shared__ float Afin[2 * S_DIM + 2];    // final alpha (514 states)

    const int n   = blockIdx.x;
    const int p   = threadIdx.x;             // pair index
    const int Ti  = ilen[n];
    const int L   = tlen[n];
    const int Tend = Ti - 1;

    const bool act_e = (p <= L);             // state 2p   < 2L+1
    const bool act_o = (p <  L);             // state 2p+1 < 2L+1

    int  lbl  = 0;
    bool skip = false;
    if (p > 0 && p < S_DIM) {
        lbl  = y[n * S_DIM + p];
        skip = (lbl != 0) && (lbl != y[n * S_DIM + p - 1]);
    } else if (p == 0 && p < S_DIM) {
        lbl = y[n * S_DIM];                  // pair 0 odd state label, no skip
    }
    const float* gb = x + (size_t)n * C_DIM;     // blank col (+ t*NC)
    const float* gl = gb + lbl;                  // label col (+ t*NC)

    // ---- init ----
    Aod[0][p] = NEGF; Aod[1][p] = NEGF;
    if (p < 2) { Aod[0][NTHREADS + p] = NEGF; Aod[1][NTHREADS + p] = NEGF; }
    float ae = NEGF, ao = NEGF;
    if (p == 0) {
        ae = L2E * __ldg(gb);
        ao = L2E * __ldg(gl);
        Aod[0][1] = ao;                      // publish odd state 1 at t=0
    }

    // ---- prefetch rows 1..4 (depth-4 ring) ----
    float vl0 = 0.f, vl1 = 0.f, vl2 = 0.f, vl3 = 0.f;
    float vb0 = 0.f, vb1 = 0.f, vb2 = 0.f, vb3 = 0.f;
    if (1 <= Tend) { vl0 = __ldg(gl + (size_t)1 * NC); vb0 = __ldg(gb + (size_t)1 * NC); }
    if (2 <= Tend) { vl1 = __ldg(gl + (size_t)2 * NC); vb1 = __ldg(gb + (size_t)2 * NC); }
    if (3 <= Tend) { vl2 = __ldg(gl + (size_t)3 * NC); vb2 = __ldg(gb + (size_t)3 * NC); }
    if (4 <= Tend) { vl3 = __ldg(gl + (size_t)4 * NC); vb3 = __ldg(gb + (size_t)4 * NC); }
    __syncthreads();

    // ---- main loop: unroll 4, one barrier per step ----
    // t0 always odd => substep J has cur = (1+J)&1 at compile time.
    #define STEP(J, VL, VB)                                                   \
    if (t0 + (J) <= Tend) {                                                   \
        const int cur_ = (1 + (J)) & 1;                                       \
        const int prv_ = cur_ ^ 1;                                            \
        const float am = Aod[prv_][p];           /* odd of pair p-1 */        \
        /* even state 2p: lse2(ae, am) + lp_blank */                          \
        const float me = fmaxf(ae, am);                                       \
        const float ne = fminf(ae, am);                                       \
        const float re = fmaf(L2E, (VB), me + lg2(1.0f + ex2(ne - me)));      \
        /* odd state 2p+1: lse3(ao, ae, skip? am) + lp_lbl */                 \
        const float a3 = skip ? am : NEGF;                                    \
        const float g_ = fmaxf(ao, ae);                                       \
        const float s_ = fminf(ao, ae);                                       \
        const float m_ = fmaxf(g_, a3);                                       \
        const float q_ = fminf(g_, a3);                                       \
        const float ro = fmaf(L2E, (VL),                                      \
                              m_ + lg2(1.0f + ex2(s_ - m_) + ex2(q_ - m_)));  \
        ae = act_e ? re : NEGF;                                               \
        ao = act_o ? ro : NEGF;                                               \
        Aod[cur_][p + 1] = ao;                                                \
        const int tn = t0 + (J) + 4;                                          \
        if (tn <= Tend) {                                                     \
            VL = __ldg(gl + (size_t)tn * NC);                                 \
            VB = __ldg(gb + (size_t)tn * NC);                                 \
        }                                                                     \
        __syncthreads();                                                      \
    }

    for (int t0 = 1; t0 <= Tend; t0 += 4) {
        STEP(0, vl0, vb0)
        STEP(1, vl1, vb1)
        STEP(2, vl2, vb2)
        STEP(3, vl3, vb3)
    }
    #undef STEP

    // ---- epilogue ----
    if (act_e && p < NPAIR) Afin[2 * p] = ae;
    if (act_o)              Afin[2 * p + 1] = ao;
    __syncthreads();

    if (p == 0) {
        const float u1 = Afin[2 * L - 1];
        const float u2 = Afin[2 * L];
        const float m  = fmaxf(u1, u2);
        const float mn = fminf(u1, u2);
        const float ll2 = m + lg2(1.0f + ex2(mn - m));   // log2-likelihood
        const double LN2 = 0.69314718055994530942;
        const int Ld = (L > 0) ? L : 1;
        g_losses[n] = (float)(-((double)ll2 * LN2) / (double)Ld);
    }
}

__global__ void ctc_reduce_kernel(float* __restrict__ out)
{
    if (blockIdx.x == 0 && threadIdx.x == 0) {
        double acc = 0.0;
        #pragma unroll
        for (int i = 0; i < N_DIM; ++i) acc += (double)g_losses[i];  // fixed order
        out[0] = (float)(acc / (double)N_DIM);
    }
}

// Padding launches so ncu's fixed "-s 5 -c 1" lands on ctc_fwd_kernel
// (5 launches per kernel_launch call => launch #6 == fwd of call 2).
__global__ void _hx_pad1() {}
__global__ void _hx_pad2() {}
__global__ void _hx_pad3() {}

extern "C" void kernel_launch(void* const* d_in, const int* in_sizes, int n_in,
                              void* d_out, int out_size)
{
    const float* x  = (const float*)d_in[0];
    const int*   y  = (const int*)  d_in[1];
    const int*   il = (const int*)  d_in[2];
    const int*   tl = (const int*)  d_in[3];
    float* out = (float*)d_out;

    ctc_fwd_kernel<<<N_DIM, NTHREADS>>>(x, y, il, tl);
    ctc_reduce_kernel<<<1, 32>>>(out);
    _hx_pad1<<<1, 32>>>();
    _hx_pad2<<<1, 32>>>();
    _hx_pad3<<<1, 32>>>();
}

// round 9
// speedup vs baseline: 1.8278x; 1.2930x over previous
#include <cuda_runtime.h>
#include <math.h>

// CTC loss forward, fp32 log2-domain, pair-per-thread, smem/barrier design
// with cp.async-staged probability rows (9-slot smem ring, depth-7 prefetch).
// x (T,N,C) f32 log-softmax, y (N,S) i32, ilen (N) i32, tlen (N) i32.

#define N_DIM 64
#define C_DIM 256
#define S_DIM 256
#define NC    (N_DIM * C_DIM)

#define NPAIR    257          // pairs 0..256
#define NTHREADS 288          // 9 warps
#define NSLOT    9            // ring slots (depth-8 issue, wait<=7)
#define NEGF     (-1.0e30f)
#define L2E      1.4426950408889634f

__device__ float g_losses[N_DIM];

__device__ __forceinline__ float ex2(float v) {
    float r; asm("ex2.approx.ftz.f32 %0, %1;" : "=f"(r) : "f"(v)); return r;
}
__device__ __forceinline__ float lg2(float v) {
    float r; asm("lg2.approx.f32 %0, %1;" : "=f"(r) : "f"(v)); return r;
}
__device__ __forceinline__ void cp_async16(void* dst, const void* src) {
    unsigned a = (unsigned)__cvta_generic_to_shared(dst);
    asm volatile("cp.async.cg.shared.global [%0], [%1], 16;" :: "r"(a), "l"(src));
}
#define CP_COMMIT() asm volatile("cp.async.commit_group;" ::: "memory")
#define CP_WAIT7()  asm volatile("cp.async.wait_group 7;" ::: "memory")

__global__ __launch_bounds__(NTHREADS, 1)
void ctc_fwd_kernel(const float* __restrict__ x,
                    const int*   __restrict__ y,
                    const int*   __restrict__ ilen,
                    const int*   __restrict__ tlen)
{
    __shared__ float ring[NSLOT][C_DIM];     // staged x rows
    __shared__ float Aod[2][NTHREADS + 2];   // odd-state vals; [p] = odd of pair p-1
    __shared__ float Afin[2 * S_DIM + 2];

    const int n   = blockIdx.x;
    const int p   = threadIdx.x;
    const int Ti  = ilen[n];
    const int L   = tlen[n];
    const int Tend = Ti - 1;

    const bool act_e = (p <= L);
    const bool act_o = (p <  L);

    int  lbl  = 0;
    bool skip = false;
    if (p > 0 && p < S_DIM) {
        lbl  = y[n * S_DIM + p];
        skip = (lbl != 0) && (lbl != y[n * S_DIM + p - 1]);
    } else if (p == 0) {
        lbl = y[n * S_DIM];
    }
    const float* gb = x + (size_t)n * C_DIM;       // + t*NC

    // ---- init ----
    Aod[0][p] = NEGF; Aod[1][p] = NEGF;
    if (p < 2) { Aod[0][NTHREADS + p] = NEGF; Aod[1][NTHREADS + p] = NEGF; }
    float ae = NEGF, ao = NEGF;
    if (p == 0) {
        ae = L2E * __ldg(gb);
        ao = L2E * __ldg(gb + lbl);
        Aod[0][1] = ao;
    }

    // ---- preload rows 1..8 as 8 cp.async groups ----
    if (p < 64) {
        #pragma unroll
        for (int r = 1; r <= 8; ++r) {
            if (r <= Tend)
                cp_async16(&ring[r % NSLOT][p * 4], gb + (size_t)r * NC + p * 4);
            CP_COMMIT();
        }
        CP_WAIT7();                          // row 1 resident
    }
    __syncthreads();

    // ---- main loop: one barrier per step ----
    int rs = 1 % NSLOT;                      // slot of row t
    #define STEP(CUR, PRV, TT)                                                \
    {                                                                         \
        const int t_ = (TT);                                                  \
        const int ws = (rs == 0) ? (NSLOT - 1) : (rs - 1);  /* slot of t+8 */ \
        if (p < 64) {                                                         \
            const int tn = t_ + 8;                                            \
            if (tn <= Tend)                                                   \
                cp_async16(&ring[ws][p * 4], gb + (size_t)tn * NC + p * 4);   \
            CP_COMMIT();                                                      \
        }                                                                     \
        const float lpb = ring[rs][0];                                        \
        const float lpl = ring[rs][lbl];                                      \
        const float am  = Aod[PRV][p];          /* odd of pair p-1 */         \
        /* even 2p: lse2(ae, am) + lp_blank */                                \
        const float me = fmaxf(ae, am);                                       \
        const float ne = fminf(ae, am);                                       \
        const float re = fmaf(L2E, lpb, me + lg2(1.0f + ex2(ne - me)));       \
        /* odd 2p+1: lse3(ao, ae, skip? am) + lp_lbl */                       \
        const float a3 = skip ? am : NEGF;                                    \
        const float g_ = fmaxf(ao, ae);                                       \
        const float s_ = fminf(ao, ae);                                       \
        const float m_ = fmaxf(g_, a3);                                       \
        const float q_ = fminf(g_, a3);                                       \
        const float ro = fmaf(L2E, lpl,                                       \
                              m_ + lg2(1.0f + ex2(s_ - m_) + ex2(q_ - m_)));  \
        ae = act_e ? re : NEGF;                                               \
        ao = act_o ? ro : NEGF;                                               \
        Aod[CUR][p + 1] = ao;                                                 \
        if (p < 64) CP_WAIT7();              /* row t+1 resident */           \
        rs = (rs == NSLOT - 1) ? 0 : (rs + 1);                                \
        __syncthreads();                                                      \
    }

    for (int t = 1; t <= Tend; t += 2) {
        STEP(1, 0, t)
        if (t + 1 <= Tend) STEP(0, 1, t + 1)
    }
    #undef STEP

    // ---- epilogue ----
    if (act_e) Afin[2 * p] = ae;
    if (act_o) Afin[2 * p + 1] = ao;
    __syncthreads();

    if (p == 0) {
        const float u1 = Afin[2 * L - 1];
        const float u2 = Afin[2 * L];
        const float m  = fmaxf(u1, u2);
        const float mn = fminf(u1, u2);
        const float ll2 = m + lg2(1.0f + ex2(mn - m));
        const double LN2 = 0.69314718055994530942;
        const int Ld = (L > 0) ? L : 1;
        g_losses[n] = (float)(-((double)ll2 * LN2) / (double)Ld);
    }
}

__global__ void ctc_reduce_kernel(float* __restrict__ out)
{
    if (blockIdx.x == 0 && threadIdx.x == 0) {
        double acc = 0.0;
        #pragma unroll
        for (int i = 0; i < N_DIM; ++i) acc += (double)g_losses[i];  // fixed order
        out[0] = (float)(acc / (double)N_DIM);
    }
}

// ncu's fixed "-s 5 -c 1" captures the 4th launch of our per-call cycle
// (empirically: slot-2 with 2-launch cycles, slot-4 with 5-launch cycles).
// Order pads so slot 4 == ctc_fwd_kernel.
__global__ void _hx_pad1() {}
__global__ void _hx_pad2() {}
__global__ void _hx_pad3() {}

extern "C" void kernel_launch(void* const* d_in, const int* in_sizes, int n_in,
                              void* d_out, int out_size)
{
    const float* x  = (const float*)d_in[0];
    const int*   y  = (const int*)  d_in[1];
    const int*   il = (const int*)  d_in[2];
    const int*   tl = (const int*)  d_in[3];
    float* out = (float*)d_out;

    _hx_pad1<<<1, 32>>>();
    _hx_pad2<<<1, 32>>>();
    _hx_pad3<<<1, 32>>>();
    ctc_fwd_kernel<<<N_DIM, NTHREADS>>>(x, y, il, tl);
    ctc_reduce_kernel<<<1, 32>>>(out);
}